// round 1
// baseline (speedup 1.0000x reference)
#include <cuda_runtime.h>
#include <cuda_bf16.h>
#include <cstdint>
#include <math.h>

// Problem dims (fixed)
#define BATCH 64
#define SEQ   512
#define IDIM  256
#define HD    1024
#define MTOT  (BATCH*SEQ)      // 32768
#define RBLK  128              // CTAs in persistent recurrent kernel
#define OUT_OFF ((size_t)BATCH*SEQ*HD)

// ---------------- scratch (device globals: no allocs allowed) ----------------
__device__ float g_xp[(size_t)MTOT * HD];                 // 128 MB
__device__ float g_gate[(size_t)3 * SEQ * BATCH * HD];    // 384 MB, [g][t][b][h]
__device__ float g_h[BATCH * HD];
__device__ float g_rh[BATCH * HD];
__device__ unsigned g_bar_count;
__device__ unsigned g_bar_gen;

// ---------------- grid-wide barrier ----------------
// __threadfence() on sm_103a emits MEMBAR.GL + CCTL.IVALL (L1D invalidate),
// which is exactly what we need for cross-SM visibility of h / rh.
__device__ __forceinline__ void grid_sync() {
    __threadfence();          // release: make this thread's STGs visible GPU-wide
    __syncthreads();
    if (threadIdx.x == 0) {
        unsigned gen = ((volatile unsigned*)&g_bar_gen)[0];
        unsigned arrived = atomicAdd(&g_bar_count, 1u);
        if (arrived == gridDim.x - 1) {
            g_bar_count = 0;
            __threadfence();
            atomicAdd(&g_bar_gen, 1u);
        } else {
            while (((volatile unsigned*)&g_bar_gen)[0] == gen) { __nanosleep(60); }
        }
    }
    __syncthreads();
    __threadfence();          // acquire + L1 invalidate: see other SMs' writes
}

__device__ __forceinline__ float sigmoidf_(float x) {
    return 1.0f / (1.0f + __expf(-x));
}

// ---------------- SGEMM: C = A[MxK] * B[KxN] + bias, optional row remap ------
// 128x128 block, 16-deep K tile, 8x8 per thread, 256 threads, double buffered.
__global__ __launch_bounds__(256, 2)
void sgemm128(const float* __restrict__ A, const float* __restrict__ B,
              const float* __restrict__ bias, float* __restrict__ C,
              int M, int N, int K, int remap)
{
    __shared__ float As[2][16][128];
    __shared__ float Bs[2][16][128];

    const int tid = threadIdx.x;
    const int bm = blockIdx.y * 128;
    const int bn = blockIdx.x * 128;

    const int tm = (tid >> 4) * 8;     // 16 row-groups
    const int tn = (tid & 15) * 8;     // 16 col-groups

    float acc[8][8];
#pragma unroll
    for (int i = 0; i < 8; ++i)
#pragma unroll
        for (int j = 0; j < 8; ++j) acc[i][j] = 0.0f;

    // global load mapping
    const int arow = tid >> 2;          // 0..63 (+64 second pass)
    const int acol = (tid & 3) * 4;     // 0..12
    const int brow = tid >> 5;          // 0..7  (+8 second pass)
    const int bcol = (tid & 31) * 4;    // 0..124

    const float* Ag = A + (size_t)(bm + arow) * K + acol;
    const float* Bg = B + (size_t)brow * N + bn + bcol;

    // preload tile 0
    {
        float4 a0 = *(const float4*)(Ag);
        float4 a1 = *(const float4*)(Ag + (size_t)64 * K);
        float4 b0 = *(const float4*)(Bg);
        float4 b1 = *(const float4*)(Bg + (size_t)8 * N);
        As[0][acol + 0][arow] = a0.x; As[0][acol + 1][arow] = a0.y;
        As[0][acol + 2][arow] = a0.z; As[0][acol + 3][arow] = a0.w;
        As[0][acol + 0][arow + 64] = a1.x; As[0][acol + 1][arow + 64] = a1.y;
        As[0][acol + 2][arow + 64] = a1.z; As[0][acol + 3][arow + 64] = a1.w;
        *(float4*)&Bs[0][brow][bcol] = b0;
        *(float4*)&Bs[0][brow + 8][bcol] = b1;
    }
    __syncthreads();

    int buf = 0;
    for (int kt = 0; kt < K; kt += 16) {
        const int nkt = kt + 16;
        const bool more = (nkt < K);
        float4 a0, a1, b0, b1;
        if (more) {
            a0 = *(const float4*)(Ag + nkt);
            a1 = *(const float4*)(Ag + (size_t)64 * K + nkt);
            b0 = *(const float4*)(Bg + (size_t)nkt * N);
            b1 = *(const float4*)(Bg + (size_t)(nkt + 8) * N);
        }
        const float (*as)[128] = As[buf];
        const float (*bs)[128] = Bs[buf];
#pragma unroll
        for (int kk = 0; kk < 16; ++kk) {
            float4 pa0 = *(const float4*)&as[kk][tm];
            float4 pa1 = *(const float4*)&as[kk][tm + 4];
            float4 pb0 = *(const float4*)&bs[kk][tn];
            float4 pb1 = *(const float4*)&bs[kk][tn + 4];
            float pa[8] = {pa0.x, pa0.y, pa0.z, pa0.w, pa1.x, pa1.y, pa1.z, pa1.w};
            float pb[8] = {pb0.x, pb0.y, pb0.z, pb0.w, pb1.x, pb1.y, pb1.z, pb1.w};
#pragma unroll
            for (int i = 0; i < 8; ++i)
#pragma unroll
                for (int j = 0; j < 8; ++j)
                    acc[i][j] = fmaf(pa[i], pb[j], acc[i][j]);
        }
        if (more) {
            const int nb = buf ^ 1;
            As[nb][acol + 0][arow] = a0.x; As[nb][acol + 1][arow] = a0.y;
            As[nb][acol + 2][arow] = a0.z; As[nb][acol + 3][arow] = a0.w;
            As[nb][acol + 0][arow + 64] = a1.x; As[nb][acol + 1][arow + 64] = a1.y;
            As[nb][acol + 2][arow + 64] = a1.z; As[nb][acol + 3][arow + 64] = a1.w;
            *(float4*)&Bs[nb][brow][bcol] = b0;
            *(float4*)&Bs[nb][brow + 8][bcol] = b1;
        }
        __syncthreads();
        buf ^= 1;
    }

    float bl[8];
#pragma unroll
    for (int j = 0; j < 8; ++j) bl[j] = bias[bn + tn + j];

#pragma unroll
    for (int i = 0; i < 8; ++i) {
        const int m = bm + tm + i;
        // remap: m = b*SEQ + s  ->  output row s*BATCH + b  (time-major gates)
        const size_t orow = remap ? ((size_t)(m & (SEQ - 1)) * BATCH + (m >> 9))
                                  : (size_t)m;
        float* crow = C + orow * N + bn + tn;
        float4 v0 = make_float4(acc[i][0] + bl[0], acc[i][1] + bl[1],
                                acc[i][2] + bl[2], acc[i][3] + bl[3]);
        float4 v1 = make_float4(acc[i][4] + bl[4], acc[i][5] + bl[5],
                                acc[i][6] + bl[6], acc[i][7] + bl[7]);
        *(float4*)(crow)     = v0;
        *(float4*)(crow + 4) = v1;
    }
}

// ---------------- persistent recurrent kernel ----------------
// 128 CTAs x 256 threads. CTA owns 8 H-columns for all three gate matrices,
// weights resident in 96KB smem for all 512 steps. Thread = (col, 2 rows).
__global__ __launch_bounds__(256, 1)
void gru_rec(const float* __restrict__ Wzh, const float* __restrict__ Wrh,
             const float* __restrict__ Wnh, float* __restrict__ out)
{
    extern __shared__ float smem[];
    float* wz_s = smem;                 // [8][1024] col-major-per-column
    float* wr_s = smem + 8 * HD;
    float* wn_s = smem + 16 * HD;

    const int tid = threadIdx.x;
    const int c0 = blockIdx.x * 8;

    // one-time weight staging (column slices, k contiguous per column)
    for (int i = tid; i < 8 * HD; i += 256) {
        const int k = i >> 3, c = i & 7;
        wz_s[c * HD + k] = Wzh[(size_t)k * HD + c0 + c];
        wr_s[c * HD + k] = Wrh[(size_t)k * HD + c0 + c];
        wn_s[c * HD + k] = Wnh[(size_t)k * HD + c0 + c];
    }
    // h0 = 0
    for (int i = blockIdx.x * 256 + tid; i < BATCH * HD; i += RBLK * 256)
        g_h[i] = 0.0f;
    grid_sync();

    const int cl  = tid & 7;
    const int col = c0 + cl;
    const int r0  = (tid >> 3) * 2;     // batch rows r0, r0+1
    const float* wzc = wz_s + cl * HD;
    const float* wrc = wr_s + cl * HD;
    const float* wnc = wn_s + cl * HD;

    const float* gz = g_gate;
    const float* gr = g_gate + (size_t)SEQ * BATCH * HD;
    const float* gn = g_gate + (size_t)2 * SEQ * BATCH * HD;

    for (int t = 0; t < SEQ; ++t) {
        // ---- Phase A: z = sig(xz + h@Wz_h), r = sig(xr + h@Wr_h), rh = r*h
        float az0 = 0.f, az1 = 0.f, ag0 = 0.f, ag1 = 0.f;
        const float4* h0p = (const float4*)(g_h + r0 * HD);
        const float4* h1p = (const float4*)(g_h + (r0 + 1) * HD);
        const float4* wz4 = (const float4*)wzc;
        const float4* wr4 = (const float4*)wrc;
#pragma unroll 4
        for (int k4 = 0; k4 < HD / 4; ++k4) {
            const float4 ha = __ldcg(h0p + k4);
            const float4 hb = __ldcg(h1p + k4);
            const float4 wz = wz4[k4];
            const float4 wr = wr4[k4];
            az0 = fmaf(ha.x, wz.x, az0); az0 = fmaf(ha.y, wz.y, az0);
            az0 = fmaf(ha.z, wz.z, az0); az0 = fmaf(ha.w, wz.w, az0);
            az1 = fmaf(hb.x, wz.x, az1); az1 = fmaf(hb.y, wz.y, az1);
            az1 = fmaf(hb.z, wz.z, az1); az1 = fmaf(hb.w, wz.w, az1);
            ag0 = fmaf(ha.x, wr.x, ag0); ag0 = fmaf(ha.y, wr.y, ag0);
            ag0 = fmaf(ha.z, wr.z, ag0); ag0 = fmaf(ha.w, wr.w, ag0);
            ag1 = fmaf(hb.x, wr.x, ag1); ag1 = fmaf(hb.y, wr.y, ag1);
            ag1 = fmaf(hb.z, wr.z, ag1); ag1 = fmaf(hb.w, wr.w, ag1);
        }
        const int gidx0 = (t * BATCH + r0) * HD + col;
        const int gidx1 = gidx0 + HD;
        const float z0 = sigmoidf_(az0 + __ldg(gz + gidx0));
        const float z1 = sigmoidf_(az1 + __ldg(gz + gidx1));
        const float rv0 = sigmoidf_(ag0 + __ldg(gr + gidx0));
        const float rv1 = sigmoidf_(ag1 + __ldg(gr + gidx1));
        const float h0v = __ldcg(g_h + r0 * HD + col);
        const float h1v = __ldcg(g_h + (r0 + 1) * HD + col);
        g_rh[r0 * HD + col]       = rv0 * h0v;
        g_rh[(r0 + 1) * HD + col] = rv1 * h1v;

        grid_sync();

        // ---- Phase B: n = tanh(xn + rh@Wn_h), h' = (1-z)n + z h
        float an0 = 0.f, an1 = 0.f;
        const float4* rh0p = (const float4*)(g_rh + r0 * HD);
        const float4* rh1p = (const float4*)(g_rh + (r0 + 1) * HD);
        const float4* wn4 = (const float4*)wnc;
#pragma unroll 4
        for (int k4 = 0; k4 < HD / 4; ++k4) {
            const float4 ra = __ldcg(rh0p + k4);
            const float4 rb = __ldcg(rh1p + k4);
            const float4 wn = wn4[k4];
            an0 = fmaf(ra.x, wn.x, an0); an0 = fmaf(ra.y, wn.y, an0);
            an0 = fmaf(ra.z, wn.z, an0); an0 = fmaf(ra.w, wn.w, an0);
            an1 = fmaf(rb.x, wn.x, an1); an1 = fmaf(rb.y, wn.y, an1);
            an1 = fmaf(rb.z, wn.z, an1); an1 = fmaf(rb.w, wn.w, an1);
        }
        const float n0 = tanhf(an0 + __ldg(gn + gidx0));
        const float n1 = tanhf(an1 + __ldg(gn + gidx1));
        const float hn0 = (1.0f - z0) * n0 + z0 * h0v;
        const float hn1 = (1.0f - z1) * n1 + z1 * h1v;
        g_h[r0 * HD + col]       = hn0;
        g_h[(r0 + 1) * HD + col] = hn1;
        out[((size_t)r0 * SEQ + t) * HD + col]       = hn0;
        out[((size_t)(r0 + 1) * SEQ + t) * HD + col] = hn1;
        if (t == SEQ - 1) {
            out[OUT_OFF + (size_t)r0 * HD + col]       = hn0;
            out[OUT_OFF + (size_t)(r0 + 1) * HD + col] = hn1;
        }
        grid_sync();
    }
}

// ---------------- launch ----------------
extern "C" void kernel_launch(void* const* d_in, const int* in_sizes, int n_in,
                              void* d_out, int out_size)
{
    const float* x  = (const float*)d_in[0];
    const float* Wi = (const float*)d_in[1];
    const float* bi = (const float*)d_in[2];
    const float* Wz = (const float*)d_in[3];
    const float* bz = (const float*)d_in[4];
    const float* Wr = (const float*)d_in[5];
    const float* br = (const float*)d_in[6];
    const float* Wn = (const float*)d_in[7];
    const float* bn = (const float*)d_in[8];
    float* out = (float*)d_out;

    float* xp;   cudaGetSymbolAddress((void**)&xp,   g_xp);
    float* gate; cudaGetSymbolAddress((void**)&gate, g_gate);

    const dim3 gg(HD / 128, MTOT / 128);   // (8, 256)

    // xp = x @ Wi + bi
    sgemm128<<<gg, 256>>>(x, Wi, bi, xp, MTOT, HD, IDIM, 0);
    // gates (time-major): xz, xr, xn  (W*[0:H] = x-part of each weight)
    sgemm128<<<gg, 256>>>(xp, Wz, bz, gate,                              MTOT, HD, HD, 1);
    sgemm128<<<gg, 256>>>(xp, Wr, br, gate + (size_t)SEQ * BATCH * HD,   MTOT, HD, HD, 1);
    sgemm128<<<gg, 256>>>(xp, Wn, bn, gate + (size_t)2 * SEQ * BATCH * HD, MTOT, HD, HD, 1);

    // persistent recurrence: weights' h-part starts at row HD
    cudaFuncSetAttribute(gru_rec, cudaFuncAttributeMaxDynamicSharedMemorySize, 24 * HD * 4);
    gru_rec<<<RBLK, 256, 24 * HD * 4>>>(Wz + (size_t)HD * HD,
                                        Wr + (size_t)HD * HD,
                                        Wn + (size_t)HD * HD, out);
}

// round 3
// speedup vs baseline: 2.7205x; 2.7205x over previous
#include <cuda_runtime.h>
#include <cuda_bf16.h>
#include <cstdint>
#include <math.h>

// Problem dims (fixed)
#define BATCH 64
#define SEQ   512
#define IDIM  256
#define HD    1024
#define MTOT  (BATCH*SEQ)      // 32768
#define RBLK  128              // CTAs in persistent recurrent kernel
#define WSTR  1028             // padded weight column stride (floats): 4112B % 128 = 16 -> conflict-free
#define OUT_OFF ((size_t)BATCH*SEQ*HD)

// ---------------- scratch (device globals: no allocs allowed) ----------------
__device__ float g_xp[(size_t)MTOT * HD];                 // 128 MB
__device__ float g_gate[(size_t)3 * SEQ * BATCH * HD];    // 384 MB, [g][t][b][h]
__device__ float g_h[BATCH * HD];
__device__ float g_rh[BATCH * HD];
__device__ unsigned g_bar_count;
__device__ unsigned g_bar_gen;

// ---------------- grid-wide barrier ----------------
// Release: all threads fence (makes h/rh STGs globally visible at L2) before
// thread0 arrives. Acquire side: h/rh are read with __ldcg (L2-direct), and
// gates/weights are immutable, so no L1 invalidate is needed after the wait.
__device__ __forceinline__ void grid_sync() {
    __threadfence();          // release: h/rh stores -> L2 visible
    __syncthreads();
    if (threadIdx.x == 0) {
        unsigned gen = ((volatile unsigned*)&g_bar_gen)[0];
        unsigned arrived = atomicAdd(&g_bar_count, 1u);
        if (arrived == gridDim.x - 1) {
            g_bar_count = 0;
            __threadfence();  // order count reset before gen bump
            atomicAdd(&g_bar_gen, 1u);
        } else {
            while (((volatile unsigned*)&g_bar_gen)[0] == gen) { __nanosleep(40); }
        }
    }
    __syncthreads();
    __threadfence_block();    // compiler/CTA ordering only; L2 reads are coherent
}

__device__ __forceinline__ float sigmoidf_(float x) {
    return 1.0f / (1.0f + __expf(-x));
}

__device__ __forceinline__ void dot4(const float4 h, const float4 w, float& a) {
    a = fmaf(h.x, w.x, a); a = fmaf(h.y, w.y, a);
    a = fmaf(h.z, w.z, a); a = fmaf(h.w, w.w, a);
}

// ---------------- SGEMM: C = A[MxK] * B[KxN] + bias, optional row remap ------
// 128x128 block, 16-deep K tile, 8x8 per thread, 256 threads, double buffered.
__global__ __launch_bounds__(256, 2)
void sgemm128(const float* __restrict__ A, const float* __restrict__ B,
              const float* __restrict__ bias, float* __restrict__ C,
              int M, int N, int K, int remap)
{
    __shared__ float As[2][16][128];
    __shared__ float Bs[2][16][128];

    const int tid = threadIdx.x;
    const int bm = blockIdx.y * 128;
    const int bn = blockIdx.x * 128;

    const int tm = (tid >> 4) * 8;     // 16 row-groups
    const int tn = (tid & 15) * 8;     // 16 col-groups

    float acc[8][8];
#pragma unroll
    for (int i = 0; i < 8; ++i)
#pragma unroll
        for (int j = 0; j < 8; ++j) acc[i][j] = 0.0f;

    const int arow = tid >> 2;          // 0..63 (+64 second pass)
    const int acol = (tid & 3) * 4;     // 0..12
    const int brow = tid >> 5;          // 0..7  (+8 second pass)
    const int bcol = (tid & 31) * 4;    // 0..124

    const float* Ag = A + (size_t)(bm + arow) * K + acol;
    const float* Bg = B + (size_t)brow * N + bn + bcol;

    {
        float4 a0 = *(const float4*)(Ag);
        float4 a1 = *(const float4*)(Ag + (size_t)64 * K);
        float4 b0 = *(const float4*)(Bg);
        float4 b1 = *(const float4*)(Bg + (size_t)8 * N);
        As[0][acol + 0][arow] = a0.x; As[0][acol + 1][arow] = a0.y;
        As[0][acol + 2][arow] = a0.z; As[0][acol + 3][arow] = a0.w;
        As[0][acol + 0][arow + 64] = a1.x; As[0][acol + 1][arow + 64] = a1.y;
        As[0][acol + 2][arow + 64] = a1.z; As[0][acol + 3][arow + 64] = a1.w;
        *(float4*)&Bs[0][brow][bcol] = b0;
        *(float4*)&Bs[0][brow + 8][bcol] = b1;
    }
    __syncthreads();

    int buf = 0;
    for (int kt = 0; kt < K; kt += 16) {
        const int nkt = kt + 16;
        const bool more = (nkt < K);
        float4 a0, a1, b0, b1;
        if (more) {
            a0 = *(const float4*)(Ag + nkt);
            a1 = *(const float4*)(Ag + (size_t)64 * K + nkt);
            b0 = *(const float4*)(Bg + (size_t)nkt * N);
            b1 = *(const float4*)(Bg + (size_t)(nkt + 8) * N);
        }
        const float (*as)[128] = As[buf];
        const float (*bs)[128] = Bs[buf];
#pragma unroll
        for (int kk = 0; kk < 16; ++kk) {
            float4 pa0 = *(const float4*)&as[kk][tm];
            float4 pa1 = *(const float4*)&as[kk][tm + 4];
            float4 pb0 = *(const float4*)&bs[kk][tn];
            float4 pb1 = *(const float4*)&bs[kk][tn + 4];
            float pa[8] = {pa0.x, pa0.y, pa0.z, pa0.w, pa1.x, pa1.y, pa1.z, pa1.w};
            float pb[8] = {pb0.x, pb0.y, pb0.z, pb0.w, pb1.x, pb1.y, pb1.z, pb1.w};
#pragma unroll
            for (int i = 0; i < 8; ++i)
#pragma unroll
                for (int j = 0; j < 8; ++j)
                    acc[i][j] = fmaf(pa[i], pb[j], acc[i][j]);
        }
        if (more) {
            const int nb = buf ^ 1;
            As[nb][acol + 0][arow] = a0.x; As[nb][acol + 1][arow] = a0.y;
            As[nb][acol + 2][arow] = a0.z; As[nb][acol + 3][arow] = a0.w;
            As[nb][acol + 0][arow + 64] = a1.x; As[nb][acol + 1][arow + 64] = a1.y;
            As[nb][acol + 2][arow + 64] = a1.z; As[nb][acol + 3][arow + 64] = a1.w;
            *(float4*)&Bs[nb][brow][bcol] = b0;
            *(float4*)&Bs[nb][brow + 8][bcol] = b1;
        }
        __syncthreads();
        buf ^= 1;
    }

    float bl[8];
#pragma unroll
    for (int j = 0; j < 8; ++j) bl[j] = bias[bn + tn + j];

#pragma unroll
    for (int i = 0; i < 8; ++i) {
        const int m = bm + tm + i;
        const size_t orow = remap ? ((size_t)(m & (SEQ - 1)) * BATCH + (m >> 9))
                                  : (size_t)m;
        float* crow = C + orow * N + bn + tn;
        float4 v0 = make_float4(acc[i][0] + bl[0], acc[i][1] + bl[1],
                                acc[i][2] + bl[2], acc[i][3] + bl[3]);
        float4 v1 = make_float4(acc[i][4] + bl[4], acc[i][5] + bl[5],
                                acc[i][6] + bl[6], acc[i][7] + bl[7]);
        *(float4*)(crow)     = v0;
        *(float4*)(crow + 4) = v1;
    }
}

// ---------------- persistent recurrent kernel ----------------
// 128 CTAs x 256 threads. CTA owns 8 H-columns; weights resident in smem with
// padded stride (conflict-free LDS.128). h/rh via L2 (.cg), double-buffered.
__global__ __launch_bounds__(256, 1)
void gru_rec(const float* __restrict__ Wzh, const float* __restrict__ Wrh,
             const float* __restrict__ Wnh, float* __restrict__ out)
{
    extern __shared__ float smem[];
    float* wz_s = smem;                  // 8 cols x WSTR
    float* wr_s = smem + 8 * WSTR;
    float* wn_s = smem + 16 * WSTR;

    const int tid = threadIdx.x;
    const int c0 = blockIdx.x * 8;

    for (int i = tid; i < 8 * HD; i += 256) {
        const int k = i >> 3, c = i & 7;
        wz_s[c * WSTR + k] = Wzh[(size_t)k * HD + c0 + c];
        wr_s[c * WSTR + k] = Wrh[(size_t)k * HD + c0 + c];
        wn_s[c * WSTR + k] = Wnh[(size_t)k * HD + c0 + c];
    }
    for (int i = blockIdx.x * 256 + tid; i < BATCH * HD; i += RBLK * 256)
        g_h[i] = 0.0f;
    grid_sync();

    const int cl  = tid & 7;
    const int col = c0 + cl;
    const int r0  = (tid >> 3) * 2;     // batch rows r0, r0+1
    const float4* wz4 = (const float4*)(wz_s + cl * WSTR);
    const float4* wr4 = (const float4*)(wr_s + cl * WSTR);
    const float4* wn4 = (const float4*)(wn_s + cl * WSTR);

    const float* gz = g_gate;
    const float* gr = g_gate + (size_t)SEQ * BATCH * HD;
    const float* gn = g_gate + (size_t)2 * SEQ * BATCH * HD;

    const float4* h0p = (const float4*)(g_h + r0 * HD);
    const float4* h1p = (const float4*)(g_h + (r0 + 1) * HD);
    const float4* rh0p = (const float4*)(g_rh + r0 * HD);
    const float4* rh1p = (const float4*)(g_rh + (r0 + 1) * HD);

    for (int t = 0; t < SEQ; ++t) {
        // ---- Phase A: z = sig(xz + h@Wz_h), r = sig(xr + h@Wr_h), rh = r*h
        float az0 = 0.f, az1 = 0.f, ar0 = 0.f, ar1 = 0.f;
        float4 A0[4], A1[4], B0[4], B1[4];

#define LOADH(b0, b1, base) { _Pragma("unroll") \
        for (int j = 0; j < 4; ++j) { b0[j] = __ldcg(h0p + (base) + j); b1[j] = __ldcg(h1p + (base) + j); } }
#define COMPA(b0, b1, base) { _Pragma("unroll") \
        for (int j = 0; j < 4; ++j) { \
            const float4 wz = wz4[(base) + j], wr = wr4[(base) + j]; \
            dot4(b0[j], wz, az0); dot4(b1[j], wz, az1); \
            dot4(b0[j], wr, ar0); dot4(b1[j], wr, ar1); } }

        LOADH(A0, A1, 0);
        for (int blk = 0; blk < 64; blk += 2) {          // 64 blocks of 4 float4 (16 k)
            LOADH(B0, B1, (blk + 1) * 4);
            COMPA(A0, A1, blk * 4);
            if (blk + 2 < 64) { LOADH(A0, A1, (blk + 2) * 4); }
            COMPA(B0, B1, (blk + 1) * 4);
        }

        const int gidx0 = (t * BATCH + r0) * HD + col;
        const int gidx1 = gidx0 + HD;
        const float z0 = sigmoidf_(az0 + __ldg(gz + gidx0));
        const float z1 = sigmoidf_(az1 + __ldg(gz + gidx1));
        const float rv0 = sigmoidf_(ar0 + __ldg(gr + gidx0));
        const float rv1 = sigmoidf_(ar1 + __ldg(gr + gidx1));
        const float h0v = __ldcg(g_h + r0 * HD + col);
        const float h1v = __ldcg(g_h + (r0 + 1) * HD + col);
        g_rh[r0 * HD + col]       = rv0 * h0v;
        g_rh[(r0 + 1) * HD + col] = rv1 * h1v;

        grid_sync();

        // ---- Phase B: n = tanh(xn + rh@Wn_h), h' = (1-z)n + z h
        float an0 = 0.f, an1 = 0.f;
        float4 C0[4], C1[4], D0[4], D1[4];

#define LOADR(b0, b1, base) { _Pragma("unroll") \
        for (int j = 0; j < 4; ++j) { b0[j] = __ldcg(rh0p + (base) + j); b1[j] = __ldcg(rh1p + (base) + j); } }
#define COMPB(b0, b1, base) { _Pragma("unroll") \
        for (int j = 0; j < 4; ++j) { \
            const float4 wn = wn4[(base) + j]; \
            dot4(b0[j], wn, an0); dot4(b1[j], wn, an1); } }

        LOADR(C0, C1, 0);
        for (int blk = 0; blk < 64; blk += 2) {
            LOADR(D0, D1, (blk + 1) * 4);
            COMPB(C0, C1, blk * 4);
            if (blk + 2 < 64) { LOADR(C0, C1, (blk + 2) * 4); }
            COMPB(D0, D1, (blk + 1) * 4);
        }

        const float n0 = tanhf(an0 + __ldg(gn + gidx0));
        const float n1 = tanhf(an1 + __ldg(gn + gidx1));
        const float hn0 = (1.0f - z0) * n0 + z0 * h0v;
        const float hn1 = (1.0f - z1) * n1 + z1 * h1v;
        g_h[r0 * HD + col]       = hn0;
        g_h[(r0 + 1) * HD + col] = hn1;
        out[((size_t)r0 * SEQ + t) * HD + col]       = hn0;
        out[((size_t)(r0 + 1) * SEQ + t) * HD + col] = hn1;
        if (t == SEQ - 1) {
            out[OUT_OFF + (size_t)r0 * HD + col]       = hn0;
            out[OUT_OFF + (size_t)(r0 + 1) * HD + col] = hn1;
        }
        grid_sync();
    }
}

// ---------------- launch ----------------
extern "C" void kernel_launch(void* const* d_in, const int* in_sizes, int n_in,
                              void* d_out, int out_size)
{
    const float* x  = (const float*)d_in[0];
    const float* Wi = (const float*)d_in[1];
    const float* bi = (const float*)d_in[2];
    const float* Wz = (const float*)d_in[3];
    const float* bz = (const float*)d_in[4];
    const float* Wr = (const float*)d_in[5];
    const float* br = (const float*)d_in[6];
    const float* Wn = (const float*)d_in[7];
    const float* bn = (const float*)d_in[8];
    float* out = (float*)d_out;

    float* xp;   cudaGetSymbolAddress((void**)&xp,   g_xp);
    float* gate; cudaGetSymbolAddress((void**)&gate, g_gate);

    const dim3 gg(HD / 128, MTOT / 128);   // (8, 256)

    // xp = x @ Wi + bi
    sgemm128<<<gg, 256>>>(x, Wi, bi, xp, MTOT, HD, IDIM, 0);
    // gates (time-major): xz, xr, xn  (W*[0:H] = x-part of each weight)
    sgemm128<<<gg, 256>>>(xp, Wz, bz, gate,                               MTOT, HD, HD, 1);
    sgemm128<<<gg, 256>>>(xp, Wr, br, gate + (size_t)SEQ * BATCH * HD,    MTOT, HD, HD, 1);
    sgemm128<<<gg, 256>>>(xp, Wn, bn, gate + (size_t)2 * SEQ * BATCH * HD, MTOT, HD, HD, 1);

    // persistent recurrence: weights' h-part starts at row HD
    cudaFuncSetAttribute(gru_rec, cudaFuncAttributeMaxDynamicSharedMemorySize, 24 * WSTR * 4);
    gru_rec<<<RBLK, 256, 24 * WSTR * 4>>>(Wz + (size_t)HD * HD,
                                          Wr + (size_t)HD * HD,
                                          Wn + (size_t)HD * HD, out);
}